// round 3
// baseline (speedup 1.0000x reference)
#include <cuda_runtime.h>
#include <cstdint>

#define TSEQ  512
#define BATCH 64
#define EMBD  512
#define HIDD  1024
#define G4    4096   // 4*HIDD
#define NBLK  128
#define NTHR  512
#define SMEM_BYTES 147456   // 2*(32KB W + 32KB X) + 16KB xp

// ---------------- scratch (static __device__ arrays; no allocation) ---------
__device__ float g_xp[(size_t)2 * TSEQ * G4 * BATCH];          // 1.07 GB
__device__ float g_hist[(size_t)2 * TSEQ * HIDD * BATCH];      // 268 MB
__device__ float g_hbuf[4 * HIDD * BATCH];                     // ping-pong h
__device__ float g_WT[(size_t)2 * HIDD * G4];                  // Whh^T [d][k][row]
__device__ unsigned g_cnt = 0;
__device__ volatile unsigned g_gen = 0;

// ---------------- f32x2 helpers --------------------------------------------
typedef unsigned long long u64;

__device__ __forceinline__ u64 dup2(float x) {
    u64 r; unsigned xi = __float_as_uint(x);
    asm("mov.b64 %0, {%1, %1};" : "=l"(r) : "r"(xi));
    return r;
}
__device__ __forceinline__ void fma2(u64 &d, u64 a, u64 b) {
    asm("fma.rn.f32x2 %0, %1, %2, %0;" : "+l"(d) : "l"(a), "l"(b));
}
__device__ __forceinline__ u64 add2(u64 a, u64 b) {
    u64 r; asm("add.rn.f32x2 %0, %1, %2;" : "=l"(r) : "l"(a), "l"(b));
    return r;
}
__device__ __forceinline__ float lo32(u64 v) { return __uint_as_float((unsigned)(v & 0xffffffffull)); }
__device__ __forceinline__ float hi32(u64 v) { return __uint_as_float((unsigned)(v >> 32)); }
__device__ __forceinline__ float sigmoidf_(float x) { return 1.0f / (1.0f + expf(-x)); }

// ---------------- cp.async helpers -----------------------------------------
__device__ __forceinline__ void cp16(void* dst, const void* src) {
    unsigned s = (unsigned)__cvta_generic_to_shared(dst);
    asm volatile("cp.async.cg.shared.global [%0], [%1], 16;" :: "r"(s), "l"(src));
}
__device__ __forceinline__ void cp_commit() { asm volatile("cp.async.commit_group;"); }
template<int N> __device__ __forceinline__ void cp_wait() {
    asm volatile("cp.async.wait_group %0;" :: "n"(N));
}

// ---------------- grid barrier ----------------------------------------------
__device__ __forceinline__ void grid_bar() {
    __syncthreads();
    if (threadIdx.x == 0) {
        unsigned my = g_gen;
        __threadfence();
        if (atomicAdd(&g_cnt, 1u) == NBLK - 1) {
            g_cnt = 0;
            __threadfence();
            g_gen = my + 1;
        } else {
            while (g_gen == my) { }
        }
    }
    __syncthreads();
}

// ---------------- Whh transpose: g_WT[d][k][row] = Whh_d[row][k] ------------
__global__ void transpose_kernel(const float* __restrict__ Wf,
                                 const float* __restrict__ Wb) {
    __shared__ float ts[32][33];
    const int d = blockIdx.z;
    const float* W = d ? Wb : Wf;
    const int k0 = blockIdx.x * 32, r0 = blockIdx.y * 32;
    const int tx = threadIdx.x, ty = threadIdx.y;   // 32 x 8
#pragma unroll
    for (int p = 0; p < 4; ++p)
        ts[ty + 8 * p][tx] = W[(size_t)(r0 + ty + 8 * p) * HIDD + k0 + tx];
    __syncthreads();
#pragma unroll
    for (int p = 0; p < 4; ++p)
        g_WT[((size_t)d * HIDD + k0 + ty + 8 * p) * G4 + r0 + tx] = ts[tx][ty + 8 * p];
}

// ---------------- x-projection (unchanged from R1 — known good) -------------
__global__ __launch_bounds__(256) void xproj_kernel(
    const int*   __restrict__ src,
    const float* __restrict__ emb,
    const float* __restrict__ Wih_f, const float* __restrict__ Wih_b,
    const float* __restrict__ bih_f, const float* __restrict__ bhh_f,
    const float* __restrict__ bih_b, const float* __restrict__ bhh_b)
{
    __shared__ float sW[64 * 36];
    __shared__ float sX[32 * 64];
    __shared__ int   sIdx[64];

    const int tid = threadIdx.x;
    const int gt  = blockIdx.x;
    const int t   = blockIdx.y;
    const int d   = blockIdx.z;

    const float* Wih = d ? Wih_b : Wih_f;
    const int t_src  = d ? (TSEQ - 1 - t) : t;

    if (tid < 64) sIdx[tid] = src[t_src * BATCH + tid];
    __syncthreads();

    const int wr = tid >> 2;
    const int wq = tid & 3;
    const float* wgp = Wih + (size_t)(gt * 64 + wr) * EMBD;
    const int xn = tid & 63;
    const int xq = tid >> 6;
    const int sidx = sIdx[xn];
    const float* erow = emb + (size_t)sidx * EMBD;
    const bool xzero = (sidx == 0);

    const int i = tid >> 4;
    const int j = tid & 15;

    u64 acc[4][2];
#pragma unroll
    for (int g = 0; g < 4; ++g) { acc[g][0] = 0ull; acc[g][1] = 0ull; }

    float4 wreg0, wreg1, xreg0, xreg1;
    wreg0 = *(const float4*)(wgp + wq * 4);
    wreg1 = *(const float4*)(wgp + wq * 4 + 16);
    if (xzero) { xreg0 = make_float4(0.f,0.f,0.f,0.f); xreg1 = xreg0; }
    else { xreg0 = *(const float4*)(erow + xq * 8); xreg1 = *(const float4*)(erow + xq * 8 + 4); }

    const int NC = EMBD / 32;
#pragma unroll 1
    for (int ch = 0; ch < NC; ++ch) {
        *(float4*)&sW[wr * 36 + wq * 4]      = wreg0;
        *(float4*)&sW[wr * 36 + wq * 4 + 16] = wreg1;
        {
            const float* x0 = (const float*)&xreg0;
            const float* x1 = (const float*)&xreg1;
#pragma unroll
            for (int s2 = 0; s2 < 4; ++s2) {
                sX[(xq * 8 + s2)     * 64 + xn] = x0[s2];
                sX[(xq * 8 + 4 + s2) * 64 + xn] = x1[s2];
            }
        }
        __syncthreads();
        if (ch + 1 < NC) {
            int k0 = (ch + 1) * 32;
            wreg0 = *(const float4*)(wgp + k0 + wq * 4);
            wreg1 = *(const float4*)(wgp + k0 + wq * 4 + 16);
            if (xzero) { xreg0 = make_float4(0.f,0.f,0.f,0.f); xreg1 = xreg0; }
            else { xreg0 = *(const float4*)(erow + k0 + xq * 8);
                   xreg1 = *(const float4*)(erow + k0 + xq * 8 + 4); }
        }
#pragma unroll
        for (int kb = 0; kb < 8; ++kb) {
            const int k4 = kb * 4;
            float4 w0 = *(const float4*)&sW[(i     ) * 36 + k4];
            float4 w1 = *(const float4*)&sW[(i + 16) * 36 + k4];
            float4 w2 = *(const float4*)&sW[(i + 32) * 36 + k4];
            float4 w3 = *(const float4*)&sW[(i + 48) * 36 + k4];
            const float* p0 = (const float*)&w0;
            const float* p1 = (const float*)&w1;
            const float* p2 = (const float*)&w2;
            const float* p3 = (const float*)&w3;
#pragma unroll
            for (int kk = 0; kk < 4; ++kk) {
                const u64* hx = (const u64*)&sX[(k4 + kk) * 64 + 4 * j];
                u64 h0 = hx[0], h1 = hx[1];
                u64 a;
                a = dup2(p0[kk]); fma2(acc[0][0], a, h0); fma2(acc[0][1], a, h1);
                a = dup2(p1[kk]); fma2(acc[1][0], a, h0); fma2(acc[1][1], a, h1);
                a = dup2(p2[kk]); fma2(acc[2][0], a, h0); fma2(acc[2][1], a, h1);
                a = dup2(p3[kk]); fma2(acc[3][0], a, h0); fma2(acc[3][1], a, h1);
            }
        }
        __syncthreads();
    }

    const float* bih = d ? bih_b : bih_f;
    const float* bhh = d ? bhh_b : bhh_f;
    float* xp = g_xp + (size_t)(d * TSEQ + t) * G4 * BATCH;
#pragma unroll
    for (int g = 0; g < 4; ++g) {
        int row = gt * 64 + i + g * 16;
        float bias = bih[row] + bhh[row];
        float4 o;
        o.x = lo32(acc[g][0]) + bias;
        o.y = hi32(acc[g][0]) + bias;
        o.z = lo32(acc[g][1]) + bias;
        o.w = hi32(acc[g][1]) + bias;
        *(float4*)&xp[(size_t)row * BATCH + 4 * j] = o;
    }
}

// ---------------- window staging (cp.async) ---------------------------------
__device__ __forceinline__ void stage_win(float* bufp, const float* WTd,
                                          const float* hprev, int win,
                                          int u0, int tid)
{
    // W: 64 rows x 128 k, WT layout [k][64 rows as 4 groups of 16]
#pragma unroll
    for (int s = 0; s < 4; ++s) {
        int c = tid * 4 + s;                 // 0..2047
        int k = c >> 4, rem = c & 15, v = rem >> 2, part = rem & 3;
        const float* src = WTd + (size_t)(win * 128 + k) * G4 + v * HIDD + u0 + part * 4;
        cp16(&bufp[k * 64 + v * 16 + part * 4], src);
    }
    float* bx = bufp + 8192;
#pragma unroll
    for (int s = 0; s < 4; ++s) {
        int c = tid * 4 + s;                 // 0..2047
        int k = c >> 4, part = c & 15;
        cp16(&bx[k * 64 + part * 4], hprev + (size_t)(win * 128 + k) * 64 + part * 4);
    }
}

// ---------------- persistent recurrence, both directions --------------------
// 128 blocks x 512 threads. block: dir = bid>>6, u0 = (bid&63)*16 (16 units x 4 gates = 64 rows)
// thread: ks = tid>>7 (K quarter), i = (tid&127)>>4 (8: row-pairs), j = tid&15 (4 batch)
__global__ __launch_bounds__(NTHR, 1) void persist_kernel()
{
    extern __shared__ float sm[];
    float* sXP = sm + 32768;              // 4096 floats
    u64*   red = (u64*)sm;                // reduction reuses buf0 (48KB)

    const int tid = threadIdx.x;
    const int bid = blockIdx.x;
    const int d   = bid >> 6;
    const int u0  = (bid & 63) * 16;
    const int ks  = tid >> 7;
    const int r   = tid & 127;
    const int i   = r >> 4;
    const int j   = r & 15;

    // zero h(-1) (parity-0 buffers, both dirs)
    {
        int z = bid * NTHR + tid;                      // 0..65535
        g_hbuf[z] = 0.0f;                              // d=0 parity 0
        g_hbuf[2 * HIDD * BATCH + z] = 0.0f;           // d=1 parity 0
    }
    float creg[2][4];
#pragma unroll
    for (int uu = 0; uu < 2; ++uu)
#pragma unroll
        for (int b = 0; b < 4; ++b) creg[uu][b] = 0.0f;

    grid_bar();

    const float* WTd = g_WT + (size_t)d * HIDD * G4;

    for (int t = 0; t < TSEQ; ++t) {
        const float* hprev = g_hbuf + (size_t)(d * 2 + (t & 1))       * (HIDD * BATCH);
        float*       hnext = g_hbuf + (size_t)(d * 2 + ((t + 1) & 1)) * (HIDD * BATCH);

        u64 acc[4][4];
#pragma unroll
        for (int v = 0; v < 4; ++v)
#pragma unroll
            for (int b = 0; b < 4; ++b) acc[v][b] = 0ull;

        // stage xp slice (64 rows x 64 b) + window 0
        const float* xpb = g_xp + (size_t)(d * TSEQ + t) * G4 * BATCH;
#pragma unroll
        for (int s = 0; s < 2; ++s) {
            int c = tid * 2 + s;               // 0..1023
            int v = c >> 8, rem = c & 255;
            cp16(&sXP[v * 1024 + rem * 4],
                 xpb + (size_t)v * HIDD * BATCH + u0 * BATCH + rem * 4);
        }
        stage_win(sm, WTd, hprev, 0, u0, tid);
        cp_commit();

#pragma unroll 1
        for (int win = 0; win < 8; ++win) {
            float* bw = sm + (win & 1) * 16384;
            float* bx = bw + 8192;
            if (win < 7) {
                stage_win(sm + ((win + 1) & 1) * 16384, WTd, hprev, win + 1, u0, tid);
                cp_commit();
                cp_wait<1>();
            } else {
                cp_wait<0>();
            }
            __syncthreads();
#pragma unroll 2
            for (int kb = 0; kb < 8; ++kb) {
                const int k0 = ks * 32 + kb * 4;
#pragma unroll
                for (int kk = 0; kk < 4; ++kk) {
                    float4 hb = *(const float4*)&bx[(k0 + kk) * 64 + 4 * j];
                    u64 h0 = dup2(hb.x), h1 = dup2(hb.y);
                    u64 h2 = dup2(hb.z), h3 = dup2(hb.w);
#pragma unroll
                    for (int v = 0; v < 4; ++v) {
                        u64 w = *(const u64*)&bw[(k0 + kk) * 64 + v * 16 + 2 * i];
                        fma2(acc[v][0], w, h0); fma2(acc[v][1], w, h1);
                        fma2(acc[v][2], w, h2); fma2(acc[v][3], w, h3);
                    }
                }
            }
            __syncthreads();
        }

        // K-split reduction through smem (buf0 area, free now)
        if (ks) {
            u64* dst = red + ((size_t)(ks - 1) * 128 + r) * 16;
#pragma unroll
            for (int v = 0; v < 4; ++v)
#pragma unroll
                for (int b = 0; b < 4; ++b) dst[v * 4 + b] = acc[v][b];
        }
        __syncthreads();

        if (ks == 0) {
#pragma unroll
            for (int v = 0; v < 4; ++v)
#pragma unroll
                for (int b = 0; b < 4; ++b) {
                    u64 s = acc[v][b];
                    s = add2(s, red[((size_t)0 * 128 + r) * 16 + v * 4 + b]);
                    s = add2(s, red[((size_t)1 * 128 + r) * 16 + v * 4 + b]);
                    s = add2(s, red[((size_t)2 * 128 + r) * 16 + v * 4 + b]);
                    acc[v][b] = s;
                }

            const int t_out = d ? (TSEQ - 1 - t) : t;
#pragma unroll
            for (int uu = 0; uu < 2; ++uu) {
                const int u = u0 + 2 * i + uu;
                float gt[4][4];
#pragma unroll
                for (int v = 0; v < 4; ++v) {
                    float4 xv = *(const float4*)&sXP[v * 1024 + (2 * i + uu) * 64 + 4 * j];
                    gt[v][0] = (uu ? hi32(acc[v][0]) : lo32(acc[v][0])) + xv.x;
                    gt[v][1] = (uu ? hi32(acc[v][1]) : lo32(acc[v][1])) + xv.y;
                    gt[v][2] = (uu ? hi32(acc[v][2]) : lo32(acc[v][2])) + xv.z;
                    gt[v][3] = (uu ? hi32(acc[v][3]) : lo32(acc[v][3])) + xv.w;
                }
                float4 hv;
                float* hl = (float*)&hv;
#pragma unroll
                for (int b = 0; b < 4; ++b) {
                    float ig = sigmoidf_(gt[0][b]);
                    float fg = sigmoidf_(gt[1][b]);
                    float gg = tanhf(gt[2][b]);
                    float og = sigmoidf_(gt[3][b]);
                    float cn = fg * creg[uu][b] + ig * gg;
                    creg[uu][b] = cn;
                    hl[b] = og * tanhf(cn);
                }
                *(float4*)&hnext[(size_t)u * BATCH + 4 * j] = hv;
                *(float4*)&g_hist[((size_t)(d * TSEQ + t_out) * HIDD + u) * BATCH + 4 * j] = hv;
            }
            __threadfence();
        }
        grid_bar();
    }
}

// ---------------- combine: out[b][t][h] = hf + hb ---------------------------
__global__ __launch_bounds__(256) void combine_kernel(float* __restrict__ out)
{
    __shared__ float s[128 * 65];
    const int uc  = blockIdx.x;
    const int t   = blockIdx.y;
    const int tid = threadIdx.x;
    const float* hf = g_hist + (size_t)t          * HIDD * BATCH;
    const float* hb = g_hist + (size_t)(TSEQ + t) * HIDD * BATCH;
    for (int x = tid; x < 128 * 64; x += 256) {
        int uu = x >> 6, b = x & 63;
        int u = uc * 128 + uu;
        s[uu * 65 + b] = hf[(size_t)u * BATCH + b] + hb[(size_t)u * BATCH + b];
    }
    __syncthreads();
    for (int x = tid; x < 128 * 64; x += 256) {
        int b = x >> 7, uu = x & 127;
        out[((size_t)b * TSEQ + t) * HIDD + uc * 128 + uu] = s[uu * 65 + b];
    }
}

// ---------------- launch -----------------------------------------------------
extern "C" void kernel_launch(void* const* d_in, const int* in_sizes, int n_in,
                              void* d_out, int out_size)
{
    const int*   src   = (const int*)  d_in[0];
    const float* emb   = (const float*)d_in[1];
    const float* Wih_f = (const float*)d_in[2];
    const float* Whh_f = (const float*)d_in[3];
    const float* bih_f = (const float*)d_in[4];
    const float* bhh_f = (const float*)d_in[5];
    const float* Wih_b = (const float*)d_in[6];
    const float* Whh_b = (const float*)d_in[7];
    const float* bih_b = (const float*)d_in[8];
    const float* bhh_b = (const float*)d_in[9];

    transpose_kernel<<<dim3(32, 128, 2), dim3(32, 8)>>>(Whh_f, Whh_b);
    xproj_kernel<<<dim3(64, 512, 2), 256>>>(src, emb, Wih_f, Wih_b,
                                            bih_f, bhh_f, bih_b, bhh_b);
    cudaFuncSetAttribute(persist_kernel,
                         cudaFuncAttributeMaxDynamicSharedMemorySize, SMEM_BYTES);
    persist_kernel<<<NBLK, NTHR, SMEM_BYTES>>>();
    combine_kernel<<<dim3(8, 512), 256>>>((float*)d_out);
}

// round 5
// speedup vs baseline: 2.5028x; 2.5028x over previous
#include <cuda_runtime.h>
#include <cuda_bf16.h>
#include <cstdint>

#define TSEQ  512
#define BATCH 64
#define EMBD  512
#define HIDD  1024
#define G4    4096

#define STRD  144            // image row bytes: 64 bf16 + 8 pad (conflict-free ldmatrix)
#define CHB   9216           // chunk bytes = 64 rows * 144
#define NCHUNK 16            // K = 1024 = 16 * 64

// ---- step kernel smem map ---------------------------------------------------
#define ST(s, w)  ((s) * 36864 + (w) * CHB)   // w: 0=Ahi 1=Alo 2=Bhi 3=Blo
#define SM_XP     73728                        // 16KB f32 [64 rows][64 b]
#define SM_GT     90112                        // gates 64 x 68 f32 = 17408
#define SMEM_STEP 107520

// ---------------- device scratch --------------------------------------------
__device__ float g_xp[(size_t)2 * TSEQ * G4 * BATCH];            // permuted [d][t][mt][prow][b]
__device__ float g_hist[(size_t)2 * TSEQ * HIDD * BATCH];
// W image: [d][hl][mt64][chunk16][64 rows][144B]
__device__ __align__(128) unsigned char g_Wt[(size_t)2 * 2 * 64 * NCHUNK * CHB];
// h image: [d][pp][hl][chunk16][64 k][144B]   (rows = k units, cols = batch)
__device__ __align__(128) unsigned char g_hT[(size_t)2 * 2 * 2 * NCHUNK * CHB];
// cell state [d][mt][u16][b64]
__device__ float g_c[2 * 64 * 16 * 64];

// ---------------- helpers ----------------------------------------------------
typedef unsigned long long u64;
__device__ __forceinline__ u64 dup2(float x) {
    u64 r; unsigned xi = __float_as_uint(x);
    asm("mov.b64 %0, {%1, %1};" : "=l"(r) : "r"(xi));
    return r;
}
__device__ __forceinline__ void fma2(u64 &d, u64 a, u64 b) {
    asm("fma.rn.f32x2 %0, %1, %2, %0;" : "+l"(d) : "l"(a), "l"(b));
}
__device__ __forceinline__ float lo32(u64 v) { return __uint_as_float((unsigned)(v & 0xffffffffull)); }
__device__ __forceinline__ float hi32(u64 v) { return __uint_as_float((unsigned)(v >> 32)); }
__device__ __forceinline__ float sigmoidf_(float x) { return 1.0f / (1.0f + expf(-x)); }

__device__ __forceinline__ uint32_t smem_u32(const void* p) {
    uint32_t a;
    asm("{ .reg .u64 t; cvta.to.shared.u64 t, %1; cvt.u32.u64 %0, t; }" : "=r"(a) : "l"(p));
    return a;
}
__device__ __forceinline__ void cp16(uint32_t dst, const void* src) {
    asm volatile("cp.async.cg.shared.global [%0], [%1], 16;" :: "r"(dst), "l"(src));
}
__device__ __forceinline__ void cp_commit() { asm volatile("cp.async.commit_group;"); }
template<int N> __device__ __forceinline__ void cp_wait() {
    asm volatile("cp.async.wait_group %0;" :: "n"(N));
}
__device__ __forceinline__ void ldm4(uint32_t* r, uint32_t a) {
    asm volatile("ldmatrix.sync.aligned.m8n8.x4.shared.b16 {%0,%1,%2,%3}, [%4];"
        : "=r"(r[0]), "=r"(r[1]), "=r"(r[2]), "=r"(r[3]) : "r"(a));
}
__device__ __forceinline__ void ldm4t(uint32_t* r, uint32_t a) {
    asm volatile("ldmatrix.sync.aligned.m8n8.x4.trans.shared.b16 {%0,%1,%2,%3}, [%4];"
        : "=r"(r[0]), "=r"(r[1]), "=r"(r[2]), "=r"(r[3]) : "r"(a));
}
__device__ __forceinline__ void mma16816(float* c, const uint32_t* a, uint32_t b0, uint32_t b1) {
    asm volatile("mma.sync.aligned.m16n8k16.row.col.f32.bf16.bf16.f32 "
        "{%0,%1,%2,%3}, {%4,%5,%6,%7}, {%8,%9}, {%0,%1,%2,%3};"
        : "+f"(c[0]), "+f"(c[1]), "+f"(c[2]), "+f"(c[3])
        : "r"(a[0]), "r"(a[1]), "r"(a[2]), "r"(a[3]), "r"(b0), "r"(b1));
}

// ---------------- init: zero h image + cell state ----------------------------
__global__ void init_kernel() {
    size_t idx = (size_t)blockIdx.x * 1024 + threadIdx.x;
    if (idx < sizeof(g_hT) / 4) ((unsigned*)g_hT)[idx] = 0u;
    if (idx < (size_t)2 * 64 * 16 * 64) g_c[idx] = 0.0f;
}

// ---------------- prep W: bf16 hi/lo split into padded image -----------------
__global__ __launch_bounds__(256) void prepw_kernel(const float* __restrict__ Wf,
                                                    const float* __restrict__ Wb) {
    const int rr = blockIdx.x;                  // original row 0..4095
    const int d  = blockIdx.y;
    const float* W = d ? Wb : Wf;
    const int v = rr >> 10, u = rr & 1023;
    const int mt = u >> 4, uu = u & 15;
    const int prow = v * 16 + uu;
    const size_t base_hi = (((size_t)(d * 2 + 0) * 64 + mt) * NCHUNK) * CHB;
    const size_t base_lo = (((size_t)(d * 2 + 1) * 64 + mt) * NCHUNK) * CHB;
    for (int k = threadIdx.x; k < HIDD; k += 256) {
        float w = W[(size_t)rr * HIDD + k];
        __nv_bfloat16 hi = __float2bfloat16(w);
        __nv_bfloat16 lo = __float2bfloat16(w - __bfloat162float(hi));
        int c = k >> 6, kl = k & 63;
        size_t off = (size_t)c * CHB + (size_t)prow * STRD + kl * 2;
        *(__nv_bfloat16*)(g_Wt + base_hi + off) = hi;
        *(__nv_bfloat16*)(g_Wt + base_lo + off) = lo;
    }
}

// ---------------- x-projection (fp32, permuted output) ----------------------
__global__ __launch_bounds__(256) void xproj_kernel(
    const int*   __restrict__ src,
    const float* __restrict__ emb,
    const float* __restrict__ Wih_f, const float* __restrict__ Wih_b,
    const float* __restrict__ bih_f, const float* __restrict__ bhh_f,
    const float* __restrict__ bih_b, const float* __restrict__ bhh_b)
{
    __shared__ float sW[64 * 36];
    __shared__ float sX[32 * 64];
    __shared__ int   sIdx[64];

    const int tid = threadIdx.x;
    const int gt  = blockIdx.x;
    const int t   = blockIdx.y;
    const int d   = blockIdx.z;

    const float* Wih = d ? Wih_b : Wih_f;
    const int t_src  = d ? (TSEQ - 1 - t) : t;

    if (tid < 64) sIdx[tid] = src[t_src * BATCH + tid];
    __syncthreads();

    const int wr = tid >> 2;
    const int wq = tid & 3;
    const float* wgp = Wih + (size_t)(gt * 64 + wr) * EMBD;
    const int xn = tid & 63;
    const int xq = tid >> 6;
    const int sidx = sIdx[xn];
    const float* erow = emb + (size_t)sidx * EMBD;
    const bool xzero = (sidx == 0);

    const int i = tid >> 4;
    const int j = tid & 15;

    u64 acc[4][2];
#pragma unroll
    for (int g = 0; g < 4; ++g) { acc[g][0] = 0ull; acc[g][1] = 0ull; }

    float4 wreg0, wreg1, xreg0, xreg1;
    wreg0 = *(const float4*)(wgp + wq * 4);
    wreg1 = *(const float4*)(wgp + wq * 4 + 16);
    if (xzero) { xreg0 = make_float4(0.f,0.f,0.f,0.f); xreg1 = xreg0; }
    else { xreg0 = *(const float4*)(erow + xq * 8); xreg1 = *(const float4*)(erow + xq * 8 + 4); }

    const int NC = EMBD / 32;
#pragma unroll 1
    for (int ch = 0; ch < NC; ++ch) {
        *(float4*)&sW[wr * 36 + wq * 4]      = wreg0;
        *(float4*)&sW[wr * 36 + wq * 4 + 16] = wreg1;
        {
            const float* x0 = (const float*)&xreg0;
            const float* x1 = (const float*)&xreg1;
#pragma unroll
            for (int s2 = 0; s2 < 4; ++s2) {
                sX[(xq * 8 + s2)     * 64 + xn] = x0[s2];
                sX[(xq * 8 + 4 + s2) * 64 + xn] = x1[s2];
            }
        }
        __syncthreads();
        if (ch + 1 < NC) {
            int k0 = (ch + 1) * 32;
            wreg0 = *(const float4*)(wgp + k0 + wq * 4);
            wreg1 = *(const float4*)(wgp + k0 + wq * 4 + 16);
            if (xzero) { xreg0 = make_float4(0.f,0.f,0.f,0.f); xreg1 = xreg0; }
            else { xreg0 = *(const float4*)(erow + k0 + xq * 8);
                   xreg1 = *(const float4*)(erow + k0 + xq * 8 + 4); }
        }
#pragma unroll
        for (int kb = 0; kb < 8; ++kb) {
            const int k4 = kb * 4;
            float4 w0 = *(const float4*)&sW[(i     ) * 36 + k4];
            float4 w1 = *(const float4*)&sW[(i + 16) * 36 + k4];
            float4 w2 = *(const float4*)&sW[(i + 32) * 36 + k4];
            float4 w3 = *(const float4*)&sW[(i + 48) * 36 + k4];
            const float* p0 = (const float*)&w0;
            const float* p1 = (const float*)&w1;
            const float* p2 = (const float*)&w2;
            const float* p3 = (const float*)&w3;
#pragma unroll
            for (int kk = 0; kk < 4; ++kk) {
                const u64* hx = (const u64*)&sX[(k4 + kk) * 64 + 4 * j];
                u64 h0 = hx[0], h1 = hx[1];
                u64 a;
                a = dup2(p0[kk]); fma2(acc[0][0], a, h0); fma2(acc[0][1], a, h1);
                a = dup2(p1[kk]); fma2(acc[1][0], a, h0); fma2(acc[1][1], a, h1);
                a = dup2(p2[kk]); fma2(acc[2][0], a, h0); fma2(acc[2][1], a, h1);
                a = dup2(p3[kk]); fma2(acc[3][0], a, h0); fma2(acc[3][1], a, h1);
            }
        }
        __syncthreads();
    }

    const float* bih = d ? bih_b : bih_f;
    const float* bhh = d ? bhh_b : bhh_f;
#pragma unroll
    for (int g = 0; g < 4; ++g) {
        int row = gt * 64 + i + g * 16;
        float bias = bih[row] + bhh[row];
        int v = row >> 10, u = row & 1023;
        int mt = u >> 4, prow = v * 16 + (u & 15);
        float4 o;
        o.x = lo32(acc[g][0]) + bias;
        o.y = hi32(acc[g][0]) + bias;
        o.z = lo32(acc[g][1]) + bias;
        o.w = hi32(acc[g][1]) + bias;
        float* xp = g_xp + (((size_t)(d * TSEQ + t) * 64 + mt) * 64 + prow) * 64;
        *(float4*)&xp[4 * j] = o;
    }
}

// ---------------- one recurrent step: HMMA GEMM + fused pointwise ------------
// grid (64, 2): mt, d.  256 threads = 8 warps (4 M x 2 N), warp tile 16x32.
__global__ __launch_bounds__(256) void step_mma(int t)
{
    extern __shared__ __align__(16) unsigned char smem[];
    const uint32_t sb = smem_u32(smem);

    const int tid  = threadIdx.x;
    const int wid  = tid >> 5;
    const int lane = tid & 31;
    const int mt   = blockIdx.x;
    const int d    = blockIdx.y;
    const int pp   = t & 1;

    const unsigned char* srcA_hi = g_Wt + (((size_t)(d * 2 + 0) * 64 + mt) * NCHUNK) * CHB;
    const unsigned char* srcA_lo = g_Wt + (((size_t)(d * 2 + 1) * 64 + mt) * NCHUNK) * CHB;
    const unsigned char* srcB_hi = g_hT + (((size_t)(d * 2 + pp) * 2 + 0) * NCHUNK) * CHB;
    const unsigned char* srcB_lo = g_hT + (((size_t)(d * 2 + pp) * 2 + 1) * NCHUNK) * CHB;

    // ---- stage chunk 0 + xp -------------------------------------------------
    {
        const float* xps = g_xp + (((size_t)(d * TSEQ + t) * 64 + mt) * 64) * 64;
#pragma unroll
        for (int s = 0; s < 4; ++s) {
            int i2 = tid + s * 256;            // 0..1023
            cp16(sb + SM_XP + i2 * 16, xps + i2 * 4);
        }
        for (int i2 = tid; i2 < 2304; i2 += 256) {
            int which = i2 / 576, off = (i2 - which * 576) * 16;
            const unsigned char* s0 = (which == 0) ? srcA_hi : (which == 1) ? srcA_lo
                                    : (which == 2) ? srcB_hi : srcB_lo;
            cp16(sb + ST(0, which) + off, s0 + off);
        }
        cp_commit();
    }

    // warp tiling + ldmatrix per-lane offsets
    const int wm = wid & 3;                  // M group (16 rows)
    const int wn = wid >> 2;                 // N group (32 cols)
    const int ti = lane >> 3, li = lane & 7;
    const uint32_t aoff  = (uint32_t)((wm * 16 + (ti & 1) * 8 + li) * STRD + (ti >> 1) * 16);
    const uint32_t boffA = (uint32_t)(((ti >> 1) * 8 + li) * STRD + (wn * 32 + (ti & 1) * 8) * 2);
    const uint32_t boffB = boffA + 16 * 2;   // n0 + 16

    float acc[4][4];
#pragma unroll
    for (int q = 0; q < 4; ++q)
#pragma unroll
        for (int l = 0; l < 4; ++l) acc[q][l] = 0.0f;

#pragma unroll 1
    for (int c = 0; c < NCHUNK; ++c) {
        if (c + 1 < NCHUNK) {
            const size_t cb = (size_t)(c + 1) * CHB;
            for (int i2 = tid; i2 < 2304; i2 += 256) {
                int which = i2 / 576, off = (i2 - which * 576) * 16;
                const unsigned char* s0 = (which == 0) ? srcA_hi : (which == 1) ? srcA_lo
                                        : (which == 2) ? srcB_hi : srcB_lo;
                cp16(sb + ST((c + 1) & 1, which) + off, s0 + cb + off);
            }
            cp_commit();
            cp_wait<1>();
        } else {
            cp_wait<0>();
        }
        __syncthreads();

        const uint32_t A_hi = sb + ST(c & 1, 0);
        const uint32_t A_lo = sb + ST(c & 1, 1);
        const uint32_t B_hi = sb + ST(c & 1, 2);
        const uint32_t B_lo = sb + ST(c & 1, 3);
#pragma unroll
        for (int kk = 0; kk < 4; ++kk) {
            uint32_t ahi[4], alo[4], bh[8], bl[8];
            ldm4(ahi, A_hi + aoff + kk * 32);
            ldm4(alo, A_lo + aoff + kk * 32);
            ldm4t(bh,     B_hi + boffA + kk * 16 * STRD);
            ldm4t(bh + 4, B_hi + boffB + kk * 16 * STRD);
            ldm4t(bl,     B_lo + boffA + kk * 16 * STRD);
            ldm4t(bl + 4, B_lo + boffB + kk * 16 * STRD);
            // hi*hi
            mma16816(acc[0], ahi, bh[0], bh[2]);
            mma16816(acc[1], ahi, bh[1], bh[3]);
            mma16816(acc[2], ahi, bh[4], bh[6]);
            mma16816(acc[3], ahi, bh[5], bh[7]);
            // lo*hi
            mma16816(acc[0], alo, bh[0], bh[2]);
            mma16816(acc[1], alo, bh[1], bh[3]);
            mma16816(acc[2], alo, bh[4], bh[6]);
            mma16816(acc[3], alo, bh[5], bh[7]);
            // hi*lo
            mma16816(acc[0], ahi, bl[0], bl[2]);
            mma16816(acc[1], ahi, bl[1], bl[3]);
            mma16816(acc[2], ahi, bl[4], bl[6]);
            mma16816(acc[3], ahi, bl[5], bl[7]);
        }
        __syncthreads();
    }

    // ---- write accs to smem gates (stride 68 f32) ---------------------------
    float* sg = (float*)(smem + SM_GT);
    {
        const int dr = lane >> 2, dc = (lane & 3) * 2;
#pragma unroll
        for (int q = 0; q < 4; ++q) {
            const int col = wn * 32 + q * 8 + dc;
            *(float2*)&sg[(wm * 16 + dr)     * 68 + col] = make_float2(acc[q][0], acc[q][1]);
            *(float2*)&sg[(wm * 16 + dr + 8) * 68 + col] = make_float2(acc[q][2], acc[q][3]);
        }
    }
    __syncthreads();

    // ---- fused pointwise LSTM ----------------------------------------------
    {
        const float* sxp = (const float*)(smem + SM_XP);
        const int u  = tid >> 4;             // 0..15
        const int b0 = (tid & 15) * 4;
        float gv[4][4];
#pragma unroll
        for (int v = 0; v < 4; ++v) {
            const int r = v * 16 + u;
            float4 xv = *(const float4*)&sxp[r * 64 + b0];
#pragma unroll
            for (int l = 0; l < 4; ++l)
                gv[v][l] = sg[r * 68 + b0 + l] + ((const float*)&xv)[l];
        }
        float* cp = g_c + (((size_t)d * 64 + mt) * 16 + u) * 64 + b0;
        float4 cv = *(float4*)cp;
        float* cl = (float*)&cv;
        float hv[4];
#pragma unroll
        for (int l = 0; l < 4; ++l) {
            float ig = sigmoidf_(gv[0][l]);
            float fg = sigmoidf_(gv[1][l]);
            float gg = tanhf(gv[2][l]);
            float og = sigmoidf_(gv[3][l]);
            float cn = fg * cl[l] + ig * gg;
            cl[l] = cn;
            hv[l] = og * tanhf(cn);
        }
        *(float4*)cp = cv;

        const int t_out = d ? (TSEQ - 1 - t) : t;
        const int ug = mt * 16 + u;
        *(float4*)&g_hist[((size_t)(d * TSEQ + t_out) * HIDD + ug) * BATCH + b0] =
            make_float4(hv[0], hv[1], hv[2], hv[3]);

        // h(t+1) bf16 hi/lo image: [d][pp^1][hl][c][kl][b]
        __nv_bfloat16 ph[4], pl[4];
#pragma unroll
        for (int l = 0; l < 4; ++l) {
            ph[l] = __float2bfloat16(hv[l]);
            pl[l] = __float2bfloat16(hv[l] - __bfloat162float(ph[l]));
        }
        const int c = ug >> 6, kl = ug & 63;
        const size_t off = (size_t)c * CHB + (size_t)kl * STRD + b0 * 2;
        unsigned char* wb_hi = g_hT + (((size_t)(d * 2 + (pp ^ 1)) * 2 + 0) * NCHUNK) * CHB;
        unsigned char* wb_lo = g_hT + (((size_t)(d * 2 + (pp ^ 1)) * 2 + 1) * NCHUNK) * CHB;
        *(u64*)(wb_hi + off) = *(u64*)ph;
        *(u64*)(wb_lo + off) = *(u64*)pl;
    }
}

// ---------------- combine: out[b][t][h] = hf + hb ---------------------------
__global__ __launch_bounds__(256) void combine_kernel(float* __restrict__ out)
{
    __shared__ float s[128 * 65];
    const int uc  = blockIdx.x;
    const int t   = blockIdx.y;
    const int tid = threadIdx.x;
    const float* hf = g_hist + (size_t)t          * HIDD * BATCH;
    const float* hb = g_hist + (size_t)(TSEQ + t) * HIDD * BATCH;
    for (int x = tid; x < 128 * 64; x += 256) {
        int uu = x >> 6, b = x & 63;
        int u = uc * 128 + uu;
        s[uu * 65 + b] = hf[(size_t)u * BATCH + b] + hb[(size_t)u * BATCH + b];
    }
    __syncthreads();
    for (int x = tid; x < 128 * 64; x += 256) {
        int b = x >> 7, uu = x & 127;
        out[((size_t)b * TSEQ + t) * HIDD + uc * 128 + uu] = s[uu * 65 + b];
    }
}

// ---------------- launch -----------------------------------------------------
extern "C" void kernel_launch(void* const* d_in, const int* in_sizes, int n_in,
                              void* d_out, int out_size)
{
    const int*   src   = (const int*)  d_in[0];
    const float* emb   = (const float*)d_in[1];
    const float* Wih_f = (const float*)d_in[2];
    const float* Whh_f = (const float*)d_in[3];
    const float* bih_f = (const float*)d_in[4];
    const float* bhh_f = (const float*)d_in[5];
    const float* Wih_b = (const float*)d_in[6];
    const float* Whh_b = (const float*)d_in[7];
    const float* bih_b = (const float*)d_in[8];
    const float* bhh_b = (const float*)d_in[9];

    cudaFuncSetAttribute(step_mma, cudaFuncAttributeMaxDynamicSharedMemorySize, SMEM_STEP);

    init_kernel<<<288, 1024>>>();
    prepw_kernel<<<dim3(4096, 2), 256>>>(Whh_f, Whh_b);
    xproj_kernel<<<dim3(64, 512, 2), 256>>>(src, emb, Wih_f, Wih_b,
                                            bih_f, bhh_f, bih_b, bhh_b);
    for (int t = 0; t < TSEQ; ++t)
        step_mma<<<dim3(64, 2), 256, SMEM_STEP>>>(t);
    combine_kernel<<<dim3(8, 512), 256>>>((float*)d_out);
}

// round 8
// speedup vs baseline: 3.4664x; 1.3850x over previous
#include <cuda_runtime.h>
#include <cuda_bf16.h>
#include <cstdint>

#define TSEQ  512
#define BATCH 64
#define EMBD  512
#define HIDD  1024
#define G4    4096

#define STRD  144            // image row bytes: 64 bf16 + 8 pad (conflict-free ldmatrix)
#define CHB   9216           // chunk bytes = 64 rows * 144
#define NCHUNK 16            // step K = 1024 = 16 * 64
#define NCX    8             // xproj K = 512 = 8 * 64

// ---- step kernel smem map (4-stage ring) ------------------------------------
#define ST4(s, w) ((s) * 36864 + (w) * CHB)    // w: 0=Ahi 1=Alo 2=Bhi 3=Blo
#define SM_XP     147456                        // 16KB f32 [64 rows][64 b]
#define SM_GT     163840                        // gates 64 x 68 f32 = 17408
#define SMEM_STEP 181248

// ---- xproj kernel smem map (2-stage ring) -----------------------------------
#define STX(s, w) ((s) * 36864 + (w) * CHB)
#define SMX_GT    73728
#define SMX_IDX   91136
#define SMEM_X    91648

// ---------------- device scratch --------------------------------------------
__device__ float g_xp[(size_t)2 * TSEQ * G4 * BATCH];            // permuted [d][t][mt][prow][b]
__device__ float g_hist[(size_t)2 * TSEQ * HIDD * BATCH];
// Whh image: [d][hl][mt64][chunk16][64 rows][144B]
__device__ __align__(128) unsigned char g_Wt[(size_t)2 * 2 * 64 * NCHUNK * CHB];
// Wih image: [d][hl][gt64][chunk8][64 rows][144B]
__device__ __align__(128) unsigned char g_WihT[(size_t)2 * 2 * 64 * NCX * CHB];
// embedding table bf16 hi/lo
__device__ __align__(128) __nv_bfloat16 g_Ehi[(size_t)32000 * EMBD];
__device__ __align__(128) __nv_bfloat16 g_Elo[(size_t)32000 * EMBD];
// h image: [d][pp][hl][chunk16][64 k][144B]
__device__ __align__(128) unsigned char g_hT[(size_t)2 * 2 * 2 * NCHUNK * CHB];
// cell state [d][mt][u16][b64]
__device__ float g_c[2 * 64 * 16 * 64];

// ---------------- helpers ----------------------------------------------------
typedef unsigned long long u64;
__device__ __forceinline__ float sigmoidf_(float x) { return 1.0f / (1.0f + expf(-x)); }

__device__ __forceinline__ uint32_t smem_u32(const void* p) {
    uint32_t a;
    asm("{ .reg .u64 t; cvta.to.shared.u64 t, %1; cvt.u32.u64 %0, t; }" : "=r"(a) : "l"(p));
    return a;
}
__device__ __forceinline__ void cp16(uint32_t dst, const void* src) {
    asm volatile("cp.async.cg.shared.global [%0], [%1], 16;" :: "r"(dst), "l"(src));
}
__device__ __forceinline__ void cp_commit() { asm volatile("cp.async.commit_group;"); }
template<int N> __device__ __forceinline__ void cp_wait() {
    asm volatile("cp.async.wait_group %0;" :: "n"(N));
}
__device__ __forceinline__ void ldm4(uint32_t* r, uint32_t a) {
    asm volatile("ldmatrix.sync.aligned.m8n8.x4.shared.b16 {%0,%1,%2,%3}, [%4];"
        : "=r"(r[0]), "=r"(r[1]), "=r"(r[2]), "=r"(r[3]) : "r"(a));
}
__device__ __forceinline__ void ldm4t(uint32_t* r, uint32_t a) {
    asm volatile("ldmatrix.sync.aligned.m8n8.x4.trans.shared.b16 {%0,%1,%2,%3}, [%4];"
        : "=r"(r[0]), "=r"(r[1]), "=r"(r[2]), "=r"(r[3]) : "r"(a));
}
__device__ __forceinline__ void mma16816(float* c, const uint32_t* a, uint32_t b0, uint32_t b1) {
    asm volatile("mma.sync.aligned.m16n8k16.row.col.f32.bf16.bf16.f32 "
        "{%0,%1,%2,%3}, {%4,%5,%6,%7}, {%8,%9}, {%0,%1,%2,%3};"
        : "+f"(c[0]), "+f"(c[1]), "+f"(c[2]), "+f"(c[3])
        : "r"(a[0]), "r"(a[1]), "r"(a[2]), "r"(a[3]), "r"(b0), "r"(b1));
}

// ---------------- init: zero h image + cell state ----------------------------
__global__ void init_kernel() {
    size_t idx = (size_t)blockIdx.x * 1024 + threadIdx.x;
    if (idx < sizeof(g_hT) / 4) ((unsigned*)g_hT)[idx] = 0u;
    if (idx < (size_t)2 * 64 * 16 * 64) g_c[idx] = 0.0f;
}

// ---------------- prep Whh image (hi/lo, permuted, padded) -------------------
__global__ __launch_bounds__(256) void prepw_kernel(const float* __restrict__ Wf,
                                                    const float* __restrict__ Wb) {
    const int rr = blockIdx.x;                  // original row 0..4095
    const int d  = blockIdx.y;
    const float* W = d ? Wb : Wf;
    const int v = rr >> 10, u = rr & 1023;
    const int mt = u >> 4, uu = u & 15;
    const int prow = v * 16 + uu;
    const size_t base_hi = (((size_t)(d * 2 + 0) * 64 + mt) * NCHUNK) * CHB;
    const size_t base_lo = (((size_t)(d * 2 + 1) * 64 + mt) * NCHUNK) * CHB;
    for (int k = threadIdx.x; k < HIDD; k += 256) {
        float w = W[(size_t)rr * HIDD + k];
        __nv_bfloat16 hi = __float2bfloat16(w);
        __nv_bfloat16 lo = __float2bfloat16(w - __bfloat162float(hi));
        int c = k >> 6, kl = k & 63;
        size_t off = (size_t)c * CHB + (size_t)prow * STRD + kl * 2;
        *(__nv_bfloat16*)(g_Wt + base_hi + off) = hi;
        *(__nv_bfloat16*)(g_Wt + base_lo + off) = lo;
    }
}

// ---------------- prep Wih image ---------------------------------------------
__global__ __launch_bounds__(256) void prepwih_kernel(const float* __restrict__ Wf,
                                                      const float* __restrict__ Wb) {
    const int rr = blockIdx.x;                  // 0..4095
    const int d  = blockIdx.y;
    const float* W = d ? Wb : Wf;
    const int gt = rr >> 6, r = rr & 63;
    const size_t base_hi = (((size_t)(d * 2 + 0) * 64 + gt) * NCX) * CHB;
    const size_t base_lo = (((size_t)(d * 2 + 1) * 64 + gt) * NCX) * CHB;
    for (int k = threadIdx.x; k < EMBD; k += 256) {
        float w = W[(size_t)rr * EMBD + k];
        __nv_bfloat16 hi = __float2bfloat16(w);
        __nv_bfloat16 lo = __float2bfloat16(w - __bfloat162float(hi));
        int c = k >> 6, kl = k & 63;
        size_t off = (size_t)c * CHB + (size_t)r * STRD + kl * 2;
        *(__nv_bfloat16*)(g_WihT + base_hi + off) = hi;
        *(__nv_bfloat16*)(g_WihT + base_lo + off) = lo;
    }
}

// ---------------- prep embedding table bf16 hi/lo (row 0 zeroed) -------------
__global__ __launch_bounds__(256) void prepe_kernel(const float* __restrict__ emb) {
    const int v = blockIdx.x;
    const size_t base = (size_t)v * EMBD;
#pragma unroll
    for (int s = 0; s < 2; ++s) {
        int k = threadIdx.x + s * 256;
        float x = (v == 0) ? 0.0f : emb[base + k];
        __nv_bfloat16 hi = __float2bfloat16(x);
        g_Ehi[base + k] = hi;
        g_Elo[base + k] = __float2bfloat16(x - __bfloat162float(hi));
    }
}

// ---------------- xproj via HMMA: xp = Wih * embed(src) + biases -------------
// grid (gt=64, t=512, d=2), 256 thr = 8 warps (4M x 2N), warp tile 16x32, K=512
__global__ __launch_bounds__(256, 2) void xproj_mma(
    const int* __restrict__ src,
    const float* __restrict__ bih_f, const float* __restrict__ bhh_f,
    const float* __restrict__ bih_b, const float* __restrict__ bhh_b)
{
    extern __shared__ __align__(16) unsigned char smem[];
    const uint32_t sb = smem_u32(smem);

    const int tid  = threadIdx.x;
    const int wid  = tid >> 5;
    const int lane = tid & 31;
    const int gt   = blockIdx.x;
    const int t    = blockIdx.y;
    const int d    = blockIdx.z;

    int* sIdx = (int*)(smem + SMX_IDX);
    if (tid < 64) sIdx[tid] = src[(d ? (TSEQ - 1 - t) : t) * BATCH + tid];
    __syncthreads();

    const unsigned char* srcA0 = g_WihT + (((size_t)(d * 2 + 0) * 64 + gt) * NCX) * CHB;
    const unsigned char* srcA1 = g_WihT + (((size_t)(d * 2 + 1) * 64 + gt) * NCX) * CHB;

    auto stage = [&](int c, int s) {
        const size_t cb = (size_t)c * CHB;
        for (int i = tid; i < 1152; i += 256) {
            int w = i / 576, off = (i - w * 576) * 16;
            cp16(sb + STX(s, w) + off, (w ? srcA1 : srcA0) + cb + off);
        }
        for (int i = tid; i < 1024; i += 256) {
            int hl = i >> 9, r = i & 511;
            int b = r >> 3, q = r & 7;
            const __nv_bfloat16* ep = (hl ? g_Elo : g_Ehi)
                + (size_t)sIdx[b] * EMBD + c * 64 + q * 8;
            cp16(sb + STX(s, 2 + hl) + b * STRD + q * 16, ep);
        }
    };

    stage(0, 0); cp_commit();
    stage(1, 1); cp_commit();

    const int wm = wid & 3;
    const int wn = wid >> 2;
    const int ti = lane >> 3, li = lane & 7;
    const uint32_t aoff = (uint32_t)((wm * 16 + (ti & 1) * 8 + li) * STRD + (ti >> 1) * 16);
    const uint32_t boff = (uint32_t)((wn * 32 + lane) * STRD);

    float acc[4][4];
#pragma unroll
    for (int q = 0; q < 4; ++q)
#pragma unroll
        for (int l = 0; l < 4; ++l) acc[q][l] = 0.0f;

#pragma unroll 1
    for (int c = 0; c < NCX; ++c) {
        if (c + 1 < NCX) {
            if (c > 0) { stage(c + 1, (c + 1) & 1); cp_commit(); }
            cp_wait<1>();
        } else {
            cp_wait<0>();
        }
        __syncthreads();
        const uint32_t A_hi = sb + STX(c & 1, 0);
        const uint32_t A_lo = sb + STX(c & 1, 1);
        const uint32_t B_hi = sb + STX(c & 1, 2);
        const uint32_t B_lo = sb + STX(c & 1, 3);
#pragma unroll
        for (int kk = 0; kk < 4; ++kk) {
            uint32_t ahi[4], alo[4], b0h[4], b1h[4], b0l[4], b1l[4];
            ldm4(ahi, A_hi + aoff + kk * 32);
            ldm4(alo, A_lo + aoff + kk * 32);
            ldm4(b0h, B_hi + boff + kk * 32);
            ldm4(b1h, B_hi + boff + kk * 32 + 16);
            ldm4(b0l, B_lo + boff + kk * 32);
            ldm4(b1l, B_lo + boff + kk * 32 + 16);
#pragma unroll
            for (int q = 0; q < 4; ++q) mma16816(acc[q], ahi, b0h[q], b1h[q]);
#pragma unroll
            for (int q = 0; q < 4; ++q) mma16816(acc[q], alo, b0h[q], b1h[q]);
#pragma unroll
            for (int q = 0; q < 4; ++q) mma16816(acc[q], ahi, b0l[q], b1l[q]);
        }
        __syncthreads();
    }

    // write accs to smem gates (stride 68 f32)
    float* sg = (float*)(smem + SMX_GT);
    {
        const int dr = lane >> 2, dc = (lane & 3) * 2;
#pragma unroll
        for (int q = 0; q < 4; ++q) {
            const int col = wn * 32 + q * 8 + dc;
            *(float2*)&sg[(wm * 16 + dr)     * 68 + col] = make_float2(acc[q][0], acc[q][1]);
            *(float2*)&sg[(wm * 16 + dr + 8) * 68 + col] = make_float2(acc[q][2], acc[q][3]);
        }
    }
    __syncthreads();

    // bias + permuted scatter to g_xp (streaming stores)
    {
        const float* bih = d ? bih_b : bih_f;
        const float* bhh = d ? bhh_b : bhh_f;
        const int r = tid >> 2, jj = tid & 3;
        const int gr = gt * 64 + r;
        const float bias = bih[gr] + bhh[gr];
        const int v = gr >> 10, u = gr & 1023;
        const int mt = u >> 4, prow = v * 16 + (u & 15);
        float* dst = g_xp + (((size_t)(d * TSEQ + t) * 64 + mt) * 64 + prow) * 64 + jj * 16;
#pragma unroll
        for (int p = 0; p < 4; ++p) {
            float4 o = *(float4*)&sg[r * 68 + jj * 16 + p * 4];
            o.x += bias; o.y += bias; o.z += bias; o.w += bias;
            __stcs((float4*)(dst + p * 4), o);
        }
    }
}

// ---------------- one recurrent step: HMMA GEMM + fused pointwise ------------
// grid (64, 2): mt, d.  256 threads = 8 warps (4M x 2N), warp tile 16x32.
// 4-stage cp.async ring, single __syncthreads per chunk.
__global__ __launch_bounds__(256) void step_mma(int t)
{
    extern __shared__ __align__(16) unsigned char smem[];
    const uint32_t sb = smem_u32(smem);

    const int tid  = threadIdx.x;
    const int wid  = tid >> 5;
    const int lane = tid & 31;
    const int mt   = blockIdx.x;
    const int d    = blockIdx.y;
    const int pp   = t & 1;

    const unsigned char* srcA_hi = g_Wt + (((size_t)(d * 2 + 0) * 64 + mt) * NCHUNK) * CHB;
    const unsigned char* srcA_lo = g_Wt + (((size_t)(d * 2 + 1) * 64 + mt) * NCHUNK) * CHB;
    const unsigned char* srcB_hi = g_hT + (((size_t)(d * 2 + pp) * 2 + 0) * NCHUNK) * CHB;
    const unsigned char* srcB_lo = g_hT + (((size_t)(d * 2 + pp) * 2 + 1) * NCHUNK) * CHB;

    auto stage = [&](int c, int s) {
        const size_t cb = (size_t)c * CHB;
        for (int i2 = tid; i2 < 2304; i2 += 256) {
            int which = i2 / 576, off = (i2 - which * 576) * 16;
            uint32_t dst = sb + ST4(s, which) + off;
            const unsigned char* s0 = (which == 0) ? srcA_hi : (which == 1) ? srcA_lo
                                    : (which == 2) ? srcB_hi : srcB_lo;
            cp16(dst, s0 + cb + off);
        }
    };

    // stage xp slice + chunks 0..2
    {
        const float* xps = g_xp + (((size_t)(d * TSEQ + t) * 64 + mt) * 64) * 64;
#pragma unroll
        for (int s = 0; s < 4; ++s) {
            int i2 = tid + s * 256;
            cp16(sb + SM_XP + i2 * 16, xps + i2 * 4);
        }
        stage(0, 0); cp_commit();
        stage(1, 1); cp_commit();
        stage(2, 2); cp_commit();
    }

    const int wm = wid & 3;
    const int wn = wid >> 2;
    const int ti = lane >> 3, li = lane & 7;
    const uint32_t aoff  = (uint32_t)((wm * 16 + (ti & 1) * 8 + li) * STRD + (ti >> 1) * 16);
    const uint32_t boffA = (uint32_t)(((ti >> 1) * 8 + li) * STRD + (wn * 32 + (ti & 1) * 8) * 2);
    const uint32_t boffB = boffA + 16 * 2;

    float acc[4][4];
#pragma unroll
    for (int q = 0; q < 4; ++q)
#pragma unroll
        for (int l = 0; l < 4; ++l) acc[q][l] = 0.0f;

#pragma unroll 1
    for (int c = 0; c < NCHUNK; ++c) {
        // wait for chunk c (outstanding groups beyond it: chunks c+1, c+2)
        if (c <= NCHUNK - 3)      cp_wait<2>();
        else if (c == NCHUNK - 2) cp_wait<1>();
        else                      cp_wait<0>();
        __syncthreads();
        // stage chunk c+3 into slot (c+3)&3 = (c-1)&3 — its last reader was
        // chunk c-1's compute, which finished before the barrier above.
        if (c + 3 < NCHUNK) { stage(c + 3, (c + 3) & 3); cp_commit(); }

        const int s = c & 3;
        const uint32_t A_hi = sb + ST4(s, 0);
        const uint32_t A_lo = sb + ST4(s, 1);
        const uint32_t B_hi = sb + ST4(s, 2);
        const uint32_t B_lo = sb + ST4(s, 3);
#pragma unroll
        for (int kk = 0; kk < 4; ++kk) {
            uint32_t ahi[4], alo[4], bh[8], bl[8];
            ldm4(ahi, A_hi + aoff + kk * 32);
            ldm4(alo, A_lo + aoff + kk * 32);
            ldm4t(bh,     B_hi + boffA + kk * 16 * STRD);
            ldm4t(bh + 4, B_hi + boffB + kk * 16 * STRD);
            ldm4t(bl,     B_lo + boffA + kk * 16 * STRD);
            ldm4t(bl + 4, B_lo + boffB + kk * 16 * STRD);
            mma16816(acc[0], ahi, bh[0], bh[2]);
            mma16816(acc[1], ahi, bh[1], bh[3]);
            mma16816(acc[2], ahi, bh[4], bh[6]);
            mma16816(acc[3], ahi, bh[5], bh[7]);
            mma16816(acc[0], alo, bh[0], bh[2]);
            mma16816(acc[1], alo, bh[1], bh[3]);
            mma16816(acc[2], alo, bh[4], bh[6]);
            mma16816(acc[3], alo, bh[5], bh[7]);
            mma16816(acc[0], ahi, bl[0], bl[2]);
            mma16816(acc[1], ahi, bl[1], bl[3]);
            mma16816(acc[2], ahi, bl[4], bl[6]);
            mma16816(acc[3], ahi, bl[5], bl[7]);
        }
    }
    __syncthreads();

    // write accs to smem gates (stride 68 f32)
    float* sg = (float*)(smem + SM_GT);
    {
        const int dr = lane >> 2, dc = (lane & 3) * 2;
#pragma unroll
        for (int q = 0; q < 4; ++q) {
            const int col = wn * 32 + q * 8 + dc;
            *(float2*)&sg[(wm * 16 + dr)     * 68 + col] = make_float2(acc[q][0], acc[q][1]);
            *(float2*)&sg[(wm * 16 + dr + 8) * 68 + col] = make_float2(acc[q][2], acc[q][3]);
        }
    }
    __syncthreads();

    // fused pointwise LSTM
    {
        const float* sxp = (const float*)(smem + SM_XP);
        const int u  = tid >> 4;
        const int b0 = (tid & 15) * 4;
        float gv[4][4];
#pragma unroll
        for (int v = 0; v < 4; ++v) {
            const int r = v * 16 + u;
            float4 xv = *(const float4*)&sxp[r * 64 + b0];
#pragma unroll
            for (int l = 0; l < 4; ++l)
                gv[v][l] = sg[r * 68 + b0 + l] + ((const float*)&xv)[l];
        }
        float* cp = g_c + (((size_t)d * 64 + mt) * 16 + u) * 64 + b0;
        float4 cv = *(float4*)cp;
        float* cl = (float*)&cv;
        float hv[4];
#pragma unroll
        for (int l = 0; l < 4; ++l) {
            float ig = sigmoidf_(gv[0][l]);
            float fg = sigmoidf_(gv[1][l]);
            float gg = tanhf(gv[2][l]);
            float og = sigmoidf_(gv[3][l]);
            float cn = fg * cl[l] + ig * gg;
            cl[l] = cn;
            hv[l] = og * tanhf(cn);
        }
        *(float4*)cp = cv;

        const int t_out = d ? (TSEQ - 1 - t) : t;
        const int ug = mt * 16 + u;
        __stcs((float4*)&g_hist[((size_t)(d * TSEQ + t_out) * HIDD + ug) * BATCH + b0],
               make_float4(hv[0], hv[1], hv[2], hv[3]));

        __nv_bfloat16 ph[4], plo[4];
#pragma unroll
        for (int l = 0; l < 4; ++l) {
            ph[l]  = __float2bfloat16(hv[l]);
            plo[l] = __float2bfloat16(hv[l] - __bfloat162float(ph[l]));
        }
        const int c = ug >> 6, kl = ug & 63;
        const size_t off = (size_t)c * CHB + (size_t)kl * STRD + b0 * 2;
        unsigned char* wb_hi = g_hT + (((size_t)(d * 2 + (pp ^ 1)) * 2 + 0) * NCHUNK) * CHB;
        unsigned char* wb_lo = g_hT + (((size_t)(d * 2 + (pp ^ 1)) * 2 + 1) * NCHUNK) * CHB;
        *(u64*)(wb_hi + off) = *(u64*)ph;
        *(u64*)(wb_lo + off) = *(u64*)plo;
    }
}

// ---------------- combine: out[b][t][h] = hf + hb ---------------------------
__global__ __launch_bounds__(256) void combine_kernel(float* __restrict__ out)
{
    __shared__ float s[128 * 65];
    const int uc  = blockIdx.x;
    const int t   = blockIdx.y;
    const int tid = threadIdx.x;
    const float* hf = g_hist + (size_t)t          * HIDD * BATCH;
    const float* hb = g_hist + (size_t)(TSEQ + t) * HIDD * BATCH;
    for (int x = tid; x < 128 * 64; x += 256) {
        int uu = x >> 6, b = x & 63;
        int u = uc * 128 + uu;
        s[uu * 65 + b] = hf[(size_t)u * BATCH + b] + hb[(size_t)u * BATCH + b];
    }
    __syncthreads();
    for (int x = tid; x < 128 * 64; x += 256) {
        int b = x >> 7, uu = x & 127;
        out[((size_t)b * TSEQ + t) * HIDD + uc * 128 + uu] = s[uu * 65 + b];
    }
}

// ---------------- launch -----------------------------------------------------
extern "C" void kernel_launch(void* const* d_in, const int* in_sizes, int n_in,
                              void* d_out, int out_size)
{
    const int*   src   = (const int*)  d_in[0];
    const float* emb   = (const float*)d_in[1];
    const float* Wih_f = (const float*)d_in[2];
    const float* Whh_f = (const float*)d_in[3];
    const float* bih_f = (const float*)d_in[4];
    const float* bhh_f = (const float*)d_in[5];
    const float* Wih_b = (const float*)d_in[6];
    const float* Whh_b = (const float*)d_in[7];
    const float* bih_b = (const float*)d_in[8];
    const float* bhh_b = (const float*)d_in[9];

    cudaFuncSetAttribute(step_mma, cudaFuncAttributeMaxDynamicSharedMemorySize, SMEM_STEP);
    cudaFuncSetAttribute(xproj_mma, cudaFuncAttributeMaxDynamicSharedMemorySize, SMEM_X);

    init_kernel<<<288, 1024>>>();
    prepw_kernel<<<dim3(4096, 2), 256>>>(Whh_f, Whh_b);
    prepwih_kernel<<<dim3(4096, 2), 256>>>(Wih_f, Wih_b);
    prepe_kernel<<<32000, 256>>>(emb);
    xproj_mma<<<dim3(64, 512, 2), 256, SMEM_X>>>(src, bih_f, bhh_f, bih_b, bhh_b);
    for (int t = 0; t < TSEQ; ++t)
        step_mma<<<dim3(64, 2), 256, SMEM_STEP>>>(t);
    combine_kernel<<<dim3(8, 512), 256>>>((float*)d_out);
}